// round 3
// baseline (speedup 1.0000x reference)
#include <cuda_runtime.h>
#include <math.h>

// Problem constants
#define BD 2
#define TT 2048
#define CC 2048
#define NH 16
#define HD 128
#define MTOT (BD * TT)   // 4096 rows of x

// Scratch (device globals: allocation-free rule)
__device__ float g_q[BD * NH * TT * HD];   // [B,H,T,D]
__device__ float g_k[BD * NH * TT * HD];
__device__ float g_v[BD * NH * TT * HD];
__device__ float g_y[BD * TT * CC];        // attention output, [B,T,C]

// ---------------------------------------------------------------------------
// SGEMM: out = A[M,K] * W[N,K]^T   (both row-major over K, "NT" form)
// BM=BN=128, BK=16, 256 threads, 8x8 per-thread microtile.
// MODE 0: QKV — blockIdx.z selects W/out, epilogue permutes to [B,H,T,D].
// MODE 1: final projection — A is g_y, W is w_o, plain [M,N] output.
// ---------------------------------------------------------------------------
#define GBM 128
#define GBN 128
#define GBK 16
#define GAS 132   // padded smem stride (2-way store conflicts only)

template <int MODE>
__global__ __launch_bounds__(256)
void sgemm_nt(const float* __restrict__ A,
              const float* __restrict__ W0,
              const float* __restrict__ W1,
              const float* __restrict__ W2,
              float* __restrict__ Oplain)
{
    const int K = CC;
    const float* Aptr;
    const float* W;
    float* outq = nullptr;
    if (MODE == 0) {
        Aptr = A;
        W    = (blockIdx.z == 0) ? W0 : (blockIdx.z == 1) ? W1 : W2;
        outq = (blockIdx.z == 0) ? g_q : (blockIdx.z == 1) ? g_k : g_v;
    } else {
        Aptr = g_y;
        W    = W0;
    }

    __shared__ float As[GBK][GAS];   // [k][m]
    __shared__ float Bs[GBK][GAS];   // [k][n]

    const int tx = threadIdx.x, ty = threadIdx.y;
    const int tid = ty * 16 + tx;
    const int rowA0 = blockIdx.y * GBM;
    const int rowB0 = blockIdx.x * GBN;

    float c[8][8];
#pragma unroll
    for (int i = 0; i < 8; i++)
#pragma unroll
        for (int j = 0; j < 8; j++) c[i][j] = 0.0f;

    const float* Ap = Aptr + (size_t)rowA0 * K;
    const float* Bp = W    + (size_t)rowB0 * K;

    for (int k0 = 0; k0 < K; k0 += GBK) {
#pragma unroll
        for (int it = 0; it < 2; it++) {
            int l   = it * 256 + tid;
            int row = l >> 2;            // 0..127
            int kq  = (l & 3) * 4;       // 0,4,8,12
            float4 va = *(const float4*)(Ap + (size_t)row * K + k0 + kq);
            As[kq + 0][row] = va.x; As[kq + 1][row] = va.y;
            As[kq + 2][row] = va.z; As[kq + 3][row] = va.w;
            float4 vb = *(const float4*)(Bp + (size_t)row * K + k0 + kq);
            Bs[kq + 0][row] = vb.x; Bs[kq + 1][row] = vb.y;
            Bs[kq + 2][row] = vb.z; Bs[kq + 3][row] = vb.w;
        }
        __syncthreads();
#pragma unroll
        for (int k = 0; k < GBK; k++) {
            float a[8], b[8];
            // Issue all four 128-bit LDS back-to-back (MLP=4) before FFMAs
            *(float4*)(a)     = *(const float4*)&As[k][ty * 8];
            *(float4*)(b)     = *(const float4*)&Bs[k][tx * 8];
            *(float4*)(a + 4) = *(const float4*)&As[k][ty * 8 + 4];
            *(float4*)(b + 4) = *(const float4*)&Bs[k][tx * 8 + 4];
#pragma unroll
            for (int i = 0; i < 8; i++)
#pragma unroll
                for (int j = 0; j < 8; j++)
                    c[i][j] += a[i] * b[j];
        }
        __syncthreads();
    }

    // Epilogue
#pragma unroll
    for (int i = 0; i < 8; i++) {
        int m = rowA0 + ty * 8 + i;
        if (MODE == 0) {
            int b = m >> 11;       // / 2048
            int t = m & 2047;
#pragma unroll
            for (int j4 = 0; j4 < 8; j4 += 4) {
                int n = rowB0 + tx * 8 + j4;
                int h = n >> 7;    // / 128
                int d = n & 127;
                float4 v = make_float4(c[i][j4], c[i][j4 + 1], c[i][j4 + 2], c[i][j4 + 3]);
                *(float4*)&outq[(((size_t)(b * NH + h)) * TT + t) * HD + d] = v;
            }
        } else {
#pragma unroll
            for (int j4 = 0; j4 < 8; j4 += 4) {
                int n = rowB0 + tx * 8 + j4;
                float4 v = make_float4(c[i][j4], c[i][j4 + 1], c[i][j4 + 2], c[i][j4 + 3]);
                *(float4*)&Oplain[(size_t)m * CC + n] = v;
            }
        }
    }
}

// ---------------------------------------------------------------------------
// Flash-attention (non-causal), fp32. 64 queries x 64 keys per tile, D=128.
// 256 threads (16x16). Thread (tx,ty): S microtile rows ty*4+i, cols tx*4+j;
// O accumulator rows ty*4+i, cols {tx*4+j, 64+tx*4+j}.
// Row-group = 16 consecutive lanes (same ty) -> shfl width-16 reductions.
// ---------------------------------------------------------------------------
#define TQ 64
#define TK 64
#define TRS 68    // transposed-tile stride ([d][row])
#define VSS 132   // V natural-tile stride  ([s][d])
#define PSS 68    // P tile stride          ([r][s])
#define ATTN_SMEM_FLOATS (128 * TRS + 128 * TRS + 64 * PSS)
#define ATTN_SMEM_BYTES  (ATTN_SMEM_FLOATS * 4)   // 87040

__global__ __launch_bounds__(256)
void attn_kernel()
{
    extern __shared__ float sm[];
    float* QsT = sm;                    // [128][TRS] : Q^T, pre-scaled
    float* KVb = sm + 128 * TRS;        // K^T [128][TRS]  OR  V [64][VSS]
    float* Ps  = KVb + 128 * TRS;       // [64][PSS]

    const int tx = threadIdx.x, ty = threadIdx.y;
    const int tid = ty * 16 + tx;
    const int bh = blockIdx.y;          // b*NH + h
    const int q0 = blockIdx.x * TQ;
    const float scale = 0.08838834764831845f;   // 1/sqrt(128)

    const float* Qg = g_q + ((size_t)bh * TT + q0) * HD;
    const float* Kg = g_k + (size_t)bh * TT * HD;
    const float* Vg = g_v + (size_t)bh * TT * HD;

    // Load Q tile transposed + pre-scaled
#pragma unroll
    for (int it = 0; it < 8; it++) {
        int f4  = (tid & 3) + it * 4;   // 0..31
        int row = tid >> 2;             // 0..63
        int d   = f4 * 4;
        float4 v = *(const float4*)(Qg + (size_t)row * HD + d);
        QsT[(d + 0) * TRS + row] = v.x * scale;
        QsT[(d + 1) * TRS + row] = v.y * scale;
        QsT[(d + 2) * TRS + row] = v.z * scale;
        QsT[(d + 3) * TRS + row] = v.w * scale;
    }

    float m_i[4], l_i[4], acc[4][8];
#pragma unroll
    for (int i = 0; i < 4; i++) {
        m_i[i] = -1e30f;
        l_i[i] = 0.0f;
#pragma unroll
        for (int j = 0; j < 8; j++) acc[i][j] = 0.0f;
    }

    for (int s0 = 0; s0 < TT; s0 += TK) {
        __syncthreads();   // prior V reads done (and Q stores visible, 1st iter)

        // Load K tile transposed into KVb
#pragma unroll
        for (int it = 0; it < 8; it++) {
            int f4  = (tid & 3) + it * 4;
            int row = tid >> 2;
            int d   = f4 * 4;
            float4 v = *(const float4*)(Kg + (size_t)(s0 + row) * HD + d);
            KVb[(d + 0) * TRS + row] = v.x;
            KVb[(d + 1) * TRS + row] = v.y;
            KVb[(d + 2) * TRS + row] = v.z;
            KVb[(d + 3) * TRS + row] = v.w;
        }
        __syncthreads();

        // S = (Q*scale) K^T  (4x4 per thread)
        float s[4][4];
#pragma unroll
        for (int i = 0; i < 4; i++)
#pragma unroll
            for (int j = 0; j < 4; j++) s[i][j] = 0.0f;

#pragma unroll 4
        for (int k = 0; k < HD; k++) {
            float a[4], b[4];
            *(float4*)a = *(const float4*)&QsT[k * TRS + ty * 4];
            *(float4*)b = *(const float4*)&KVb[k * TRS + tx * 4];
#pragma unroll
            for (int i = 0; i < 4; i++)
#pragma unroll
                for (int j = 0; j < 4; j++)
                    s[i][j] += a[i] * b[j];
        }

        // Online softmax per row, write P tile
#pragma unroll
        for (int i = 0; i < 4; i++) {
            float mx = fmaxf(fmaxf(s[i][0], s[i][1]), fmaxf(s[i][2], s[i][3]));
#pragma unroll
            for (int off = 1; off < 16; off <<= 1)
                mx = fmaxf(mx, __shfl_xor_sync(0xffffffffu, mx, off, 16));
            float mnew = fmaxf(m_i[i], mx);
            float corr = __expf(m_i[i] - mnew);
            float rs = 0.0f;
#pragma unroll
            for (int j = 0; j < 4; j++) {
                float p = __expf(s[i][j] - mnew);
                s[i][j] = p;
                rs += p;
            }
#pragma unroll
            for (int off = 1; off < 16; off <<= 1)
                rs += __shfl_xor_sync(0xffffffffu, rs, off, 16);
            l_i[i] = l_i[i] * corr + rs;
            m_i[i] = mnew;
#pragma unroll
            for (int j = 0; j < 8; j++) acc[i][j] *= corr;
            *(float4*)&Ps[(ty * 4 + i) * PSS + tx * 4] =
                make_float4(s[i][0], s[i][1], s[i][2], s[i][3]);
        }
        __syncthreads();   // Ps complete; K-tile reads complete

        // Load V tile (natural layout) into KVb
#pragma unroll
        for (int it = 0; it < 8; it++) {
            int l   = it * 256 + tid;
            int row = l >> 5;           // 0..63
            int f4  = l & 31;
            *(float4*)&KVb[row * VSS + f4 * 4] =
                *(const float4*)(Vg + (size_t)(s0 + row) * HD + f4 * 4);
        }
        __syncthreads();

        // acc += P @ V
        for (int s4 = 0; s4 < TK; s4 += 4) {
            float p[4][4];
#pragma unroll
            for (int i = 0; i < 4; i++)
                *(float4*)p[i] = *(const float4*)&Ps[(ty * 4 + i) * PSS + s4];
#pragma unroll
            for (int ss = 0; ss < 4; ss++) {
                float4 v0 = *(const float4*)&KVb[(s4 + ss) * VSS + tx * 4];
                float4 v1 = *(const float4*)&KVb[(s4 + ss) * VSS + 64 + tx * 4];
#pragma unroll
                for (int i = 0; i < 4; i++) {
                    float pv = p[i][ss];
                    acc[i][0] += pv * v0.x; acc[i][1] += pv * v0.y;
                    acc[i][2] += pv * v0.z; acc[i][3] += pv * v0.w;
                    acc[i][4] += pv * v1.x; acc[i][5] += pv * v1.y;
                    acc[i][6] += pv * v1.z; acc[i][7] += pv * v1.w;
                }
            }
        }
    }

    // Normalize and write to g_y in [B,T,C] layout
    const int b = bh >> 4;   // / NH
    const int h = bh & 15;
#pragma unroll
    for (int i = 0; i < 4; i++) {
        float inv = 1.0f / l_i[i];
        int t = q0 + ty * 4 + i;
        float* yp = g_y + ((size_t)(b * TT + t)) * CC + h * HD;
        *(float4*)(yp + tx * 4) =
            make_float4(acc[i][0] * inv, acc[i][1] * inv, acc[i][2] * inv, acc[i][3] * inv);
        *(float4*)(yp + 64 + tx * 4) =
            make_float4(acc[i][4] * inv, acc[i][5] * inv, acc[i][6] * inv, acc[i][7] * inv);
    }
}

// ---------------------------------------------------------------------------
// Launch
// ---------------------------------------------------------------------------
extern "C" void kernel_launch(void* const* d_in, const int* in_sizes, int n_in,
                              void* d_out, int out_size)
{
    const float* x  = (const float*)d_in[0];
    const float* wq = (const float*)d_in[1];
    const float* wk = (const float*)d_in[2];
    const float* wv = (const float*)d_in[3];
    const float* wo = (const float*)d_in[4];
    float* out = (float*)d_out;

    cudaFuncSetAttribute(attn_kernel,
                         cudaFuncAttributeMaxDynamicSharedMemorySize,
                         ATTN_SMEM_BYTES);

    dim3 blk(16, 16);

    // Q/K/V projections (permuted epilogue into [B,H,T,D])
    sgemm_nt<0><<<dim3(CC / GBN, MTOT / GBM, 3), blk>>>(x, wq, wk, wv, nullptr);

    // Attention -> g_y [B,T,C]
    attn_kernel<<<dim3(TT / TQ, BD * NH), blk, ATTN_SMEM_BYTES>>>();

    // Output projection -> d_out
    sgemm_nt<1><<<dim3(CC / GBN, MTOT / GBM, 1), blk>>>(nullptr, wo, nullptr, nullptr, out);
}

// round 6
// speedup vs baseline: 2.2964x; 2.2964x over previous
#include <cuda_runtime.h>
#include <cuda_bf16.h>
#include <cstdint>

#define BD 2
#define TT 2048
#define CC 2048
#define NH 16
#define HD 128
#define MTOT (BD*TT)
#define BHH (BD*NH)
typedef __nv_bfloat16 bf16;
typedef __nv_bfloat162 bf162;

__device__ bf16 g_xhi[MTOT*CC], g_xlo[MTOT*CC];
__device__ bf16 g_whi[4][CC*CC], g_wlo[4][CC*CC];
__device__ bf16 g_qhi[BHH*TT*HD], g_qlo[BHH*TT*HD];
__device__ bf16 g_khi[BHH*TT*HD], g_klo[BHH*TT*HD];
__device__ bf16 g_vthi[BHH*HD*TT], g_vtlo[BHH*HD*TT];
__device__ float g_S[(size_t)BHH*TT*TT];
__device__ bf16 g_phi[(size_t)BHH*TT*TT], g_plo[(size_t)BHH*TT*TT];
__device__ bf16 g_yhi[MTOT*CC], g_ylo[MTOT*CC];

// ---- helpers ----
__device__ __forceinline__ uint32_t su32(const void* p){
    uint32_t a; asm("{.reg .u64 t; cvta.to.shared.u64 t,%1; cvt.u32.u64 %0,t;}":"=r"(a):"l"(p)); return a;
}
#define CP_ASYNC16(s,g) asm volatile("cp.async.cg.shared.global [%0], [%1], 16;" ::"r"(s),"l"(g))
#define CP_COMMIT() asm volatile("cp.async.commit_group;" ::: "memory")
#define LDSM4(r0,r1,r2,r3,addr) \
    asm volatile("ldmatrix.sync.aligned.m8n8.x4.shared.b16 {%0,%1,%2,%3},[%4];" \
                 :"=r"(r0),"=r"(r1),"=r"(r2),"=r"(r3):"r"(addr))

__device__ __forceinline__ void mma16816(float* d, const uint32_t* a, const uint32_t* b){
    asm volatile("mma.sync.aligned.m16n8k16.row.col.f32.bf16.bf16.f32 "
        "{%0,%1,%2,%3},{%4,%5,%6,%7},{%8,%9},{%0,%1,%2,%3};"
        : "+f"(d[0]),"+f"(d[1]),"+f"(d[2]),"+f"(d[3])
        : "r"(a[0]),"r"(a[1]),"r"(a[2]),"r"(a[3]),"r"(b[0]),"r"(b[1]));
}

__device__ __forceinline__ void split1(float v, bf16& h, bf16& l){
    h = __float2bfloat16(v); l = __float2bfloat16(v - __bfloat162float(h));
}

// ---- split fp32 -> bf16 hi/lo ----
template<int DST>
__global__ __launch_bounds__(256) void split_k(const float* __restrict__ s){
    bf16 *Hi, *Lo;
    if (DST==0){Hi=g_xhi;Lo=g_xlo;} else {Hi=g_whi[DST-1];Lo=g_wlo[DST-1];}
    int i = blockIdx.x*256 + threadIdx.x;
    float4 v = ((const float4*)s)[i];
    bf16 h0,l0,h1,l1,h2,l2,h3,l3;
    split1(v.x,h0,l0); split1(v.y,h1,l1); split1(v.z,h2,l2); split1(v.w,h3,l3);
    ((bf162*)Hi)[2*i  ] = __halves2bfloat162(h0,h1);
    ((bf162*)Hi)[2*i+1] = __halves2bfloat162(h2,h3);
    ((bf162*)Lo)[2*i  ] = __halves2bfloat162(l0,l1);
    ((bf162*)Lo)[2*i+1] = __halves2bfloat162(l2,l3);
}

// ---- warp-MMA GEMM: C[m,n] = sum_k A[m,k]*B[n,k], 3-pass bf16 split ----
// EPI: 0=Q 1=K 2=V^T 3=S 4=PV->y 5=out-proj
// Block tile 128x128, BK=64. 8 warps: wm=wid&1 (2x64), wn=wid>>1 (4x32).
#define BK 64
#define AS 72                   // smem halves per row (144B, ldmatrix conflict-free)
#define TILE_B (128*AS*2)       // 18432 B
#define SMEM_DYN (4*TILE_B)     // A0,A1,B0,B1

template<int EPI>
__global__ __launch_bounds__(256) void tc_gemm(float* __restrict__ outf)
{
    extern __shared__ bf16 smem[];
    uint32_t sb = su32(smem);
    const int tid = threadIdx.x, wid = tid>>5, lane = tid&31;
    const int wm = wid&1, wn = wid>>1;
    const int n0 = blockIdx.x*128, m0 = blockIdx.y*128, z = blockIdx.z;

    const bf16 *Ahi,*Alo,*Bhi,*Blo; int K;
    if (EPI<=2){ Ahi=g_xhi; Alo=g_xlo; Bhi=g_whi[EPI]; Blo=g_wlo[EPI]; K=CC; }
    else if (EPI==3){ size_t zo=(size_t)z*TT*HD;
        Ahi=g_qhi+zo; Alo=g_qlo+zo; Bhi=g_khi+zo; Blo=g_klo+zo; K=HD; }
    else if (EPI==4){ size_t za=(size_t)z*TT*TT, zb=(size_t)z*HD*TT;
        Ahi=g_phi+za; Alo=g_plo+za; Bhi=g_vthi+zb; Blo=g_vtlo+zb; K=TT; }
    else { Ahi=g_yhi; Alo=g_ylo; Bhi=g_whi[3]; Blo=g_wlo[3]; K=CC; }
    const int Kp = K/BK, NC = 3*Kp;

    auto load_chunk = [&](int c, int b){
        int pass = c/Kp, kk = (c - pass*Kp)*BK;
        const bf16* Ap = pass<2 ? Ahi : Alo;
        const bf16* Bp = pass==1 ? Blo : Bhi;
        uint32_t sa = sb + b*TILE_B;
        uint32_t sB = sb + 2*TILE_B + b*TILE_B;
#pragma unroll
        for (int j=0;j<4;j++){
            int lin = j*256+tid, row = lin>>3, c16 = lin&7;
            CP_ASYNC16(sa + row*(AS*2) + c16*16, Ap + (size_t)(m0+row)*K + kk + c16*8);
        }
#pragma unroll
        for (int j=0;j<4;j++){
            int lin = j*256+tid, row = lin>>3, c16 = lin&7;
            CP_ASYNC16(sB + row*(AS*2) + c16*16, Bp + (size_t)(n0+row)*K + kk + c16*8);
        }
        CP_COMMIT();
    };

    float acc[4][4][4];
#pragma unroll
    for (int mi=0;mi<4;mi++)
#pragma unroll
        for (int ni=0;ni<4;ni++)
#pragma unroll
            for (int r=0;r<4;r++) acc[mi][ni][r] = 0.0f;

    load_chunk(0,0);
    for (int c=0;c<NC;c++){
        if (c+1<NC){ load_chunk(c+1,(c+1)&1); asm volatile("cp.async.wait_group 1;":::"memory"); }
        else asm volatile("cp.async.wait_group 0;":::"memory");
        __syncthreads();
        uint32_t sa = sb + (c&1)*TILE_B;
        uint32_t sB = sb + 2*TILE_B + (c&1)*TILE_B;
#pragma unroll
        for (int ks=0;ks<BK;ks+=16){
            uint32_t af[4][4], bfr[4][2];
#pragma unroll
            for (int mi=0;mi<4;mi++){
                int r = wm*64 + mi*16 + (lane&15);
                uint32_t addr = sa + r*(AS*2) + (ks + ((lane>>4)<<3))*2;
                LDSM4(af[mi][0],af[mi][1],af[mi][2],af[mi][3], addr);
            }
#pragma unroll
            for (int g=0;g<2;g++){
                int nr = wn*32 + g*16 + ((lane>>4)<<3) + (lane&7);
                uint32_t addr = sB + nr*(AS*2) + (ks + ((lane>>3)&1)*8)*2;
                uint32_t r0,r1,r2,r3;
                LDSM4(r0,r1,r2,r3, addr);
                bfr[2*g][0]=r0; bfr[2*g][1]=r1; bfr[2*g+1][0]=r2; bfr[2*g+1][1]=r3;
            }
#pragma unroll
            for (int mi=0;mi<4;mi++)
#pragma unroll
                for (int ni=0;ni<4;ni++)
                    mma16816(acc[mi][ni], af[mi], bfr[ni]);
        }
        __syncthreads();
    }

    // ---- epilogue: thread holds rows (r0, r0+8), cols (c0, c0+1) per tile ----
    const int lrow = lane>>2, lcol = (lane&3)*2;
#pragma unroll
    for (int mi=0;mi<4;mi++){
#pragma unroll
        for (int ni=0;ni<4;ni++){
            int cw = wn*32 + ni*8 + lcol;          // col within 128-tile
            int n  = n0 + cw;
#pragma unroll
            for (int half=0; half<2; half++){
                int m = m0 + wm*64 + mi*16 + lrow + half*8;
                float v0 = acc[mi][ni][2*half], v1 = acc[mi][ni][2*half+1];
                if (EPI==0 || EPI==1){
                    if (EPI==0){ v0 *= 0.08838834764831845f; v1 *= 0.08838834764831845f; }
                    int b = m>>11, t = m&(TT-1), h = blockIdx.x, d = cw;
                    bf16* Hi = (EPI==0)?g_qhi:g_khi;  bf16* Lo = (EPI==0)?g_qlo:g_klo;
                    bf16 h0,l0,h1,l1; split1(v0,h0,l0); split1(v1,h1,l1);
                    size_t o = ((size_t)(b*NH+h)*TT + t)*HD + d;
                    *(bf162*)&Hi[o] = __halves2bfloat162(h0,h1);
                    *(bf162*)&Lo[o] = __halves2bfloat162(l0,l1);
                } else if (EPI==2){
                    int b = m>>11, t = m&(TT-1), h = blockIdx.x, d = cw;
                    bf16 h0,l0,h1,l1; split1(v0,h0,l0); split1(v1,h1,l1);
                    size_t o = ((size_t)(b*NH+h)*HD + d)*TT + t;
                    g_vthi[o] = h0; g_vtlo[o] = l0;
                    g_vthi[o+TT] = h1; g_vtlo[o+TT] = l1;
                } else if (EPI==3){
                    float* So = g_S + ((size_t)z*TT + m)*TT + n;
                    *(float2*)So = make_float2(v0, v1);
                } else if (EPI==4){
                    int b = z>>4, h = z&15, t = m, d = cw;
                    bf16 h0,l0,h1,l1; split1(v0,h0,l0); split1(v1,h1,l1);
                    size_t o = ((size_t)b*TT + t)*CC + h*HD + d;
                    *(bf162*)&g_yhi[o] = __halves2bfloat162(h0,h1);
                    *(bf162*)&g_ylo[o] = __halves2bfloat162(l0,l1);
                } else {
                    *(float2*)&outf[(size_t)m*CC + n] = make_float2(v0, v1);
                }
            }
        }
    }
}

// ---- softmax over rows of g_S, writes split P ----
__global__ __launch_bounds__(256) void softmax_k(){
    size_t row = blockIdx.x;
    const float* Sp = g_S + row*TT;
    int tid = threadIdx.x;
    __shared__ float red[8];
    float4 v0 = ((const float4*)Sp)[tid], v1 = ((const float4*)Sp)[tid+256];
    float mx = fmaxf(fmaxf(fmaxf(v0.x,v0.y),fmaxf(v0.z,v0.w)),
                     fmaxf(fmaxf(v1.x,v1.y),fmaxf(v1.z,v1.w)));
#pragma unroll
    for (int o=16;o;o>>=1) mx = fmaxf(mx,__shfl_xor_sync(~0u,mx,o));
    if (!(tid&31)) red[tid>>5] = mx;
    __syncthreads();
    mx = fmaxf(fmaxf(fmaxf(red[0],red[1]),fmaxf(red[2],red[3])),
               fmaxf(fmaxf(red[4],red[5]),fmaxf(red[6],red[7])));
    float e[8] = {__expf(v0.x-mx),__expf(v0.y-mx),__expf(v0.z-mx),__expf(v0.w-mx),
                  __expf(v1.x-mx),__expf(v1.y-mx),__expf(v1.z-mx),__expf(v1.w-mx)};
    float s = e[0]+e[1]+e[2]+e[3]+e[4]+e[5]+e[6]+e[7];
#pragma unroll
    for (int o=16;o;o>>=1) s += __shfl_xor_sync(~0u,s,o);
    __syncthreads();
    if (!(tid&31)) red[tid>>5] = s;
    __syncthreads();
    s = red[0]+red[1]+red[2]+red[3]+red[4]+red[5]+red[6]+red[7];
    float inv = 1.0f/s;
    bf162* Ph = (bf162*)(g_phi + row*TT);
    bf162* Pl = (bf162*)(g_plo + row*TT);
#pragma unroll
    for (int q=0;q<4;q++){
        float p0 = e[2*q]*inv, p1 = e[2*q+1]*inv;
        bf16 h0,l0,h1,l1; split1(p0,h0,l0); split1(p1,h1,l1);
        int idx = (q<2) ? (tid*2+q) : (512 + tid*2 + (q-2));
        Ph[idx] = __halves2bfloat162(h0,h1);
        Pl[idx] = __halves2bfloat162(l0,l1);
    }
}

// ---- launch ----
extern "C" void kernel_launch(void* const* d_in, const int* in_sizes, int n_in,
                              void* d_out, int out_size)
{
    const float* x  = (const float*)d_in[0];
    const float* wq = (const float*)d_in[1];
    const float* wk = (const float*)d_in[2];
    const float* wv = (const float*)d_in[3];
    const float* wo = (const float*)d_in[4];
    float* out = (float*)d_out;

    cudaFuncSetAttribute(tc_gemm<0>, cudaFuncAttributeMaxDynamicSharedMemorySize, SMEM_DYN);
    cudaFuncSetAttribute(tc_gemm<1>, cudaFuncAttributeMaxDynamicSharedMemorySize, SMEM_DYN);
    cudaFuncSetAttribute(tc_gemm<2>, cudaFuncAttributeMaxDynamicSharedMemorySize, SMEM_DYN);
    cudaFuncSetAttribute(tc_gemm<3>, cudaFuncAttributeMaxDynamicSharedMemorySize, SMEM_DYN);
    cudaFuncSetAttribute(tc_gemm<4>, cudaFuncAttributeMaxDynamicSharedMemorySize, SMEM_DYN);
    cudaFuncSetAttribute(tc_gemm<5>, cudaFuncAttributeMaxDynamicSharedMemorySize, SMEM_DYN);

    split_k<0><<<MTOT*CC/1024, 256>>>(x);
    split_k<1><<<CC*CC/1024, 256>>>(wq);
    split_k<2><<<CC*CC/1024, 256>>>(wk);
    split_k<3><<<CC*CC/1024, 256>>>(wv);
    split_k<4><<<CC*CC/1024, 256>>>(wo);

    tc_gemm<0><<<dim3(16,32), 256, SMEM_DYN>>>(nullptr);      // Q
    tc_gemm<1><<<dim3(16,32), 256, SMEM_DYN>>>(nullptr);      // K
    tc_gemm<2><<<dim3(16,32), 256, SMEM_DYN>>>(nullptr);      // V^T
    tc_gemm<3><<<dim3(16,16,BHH), 256, SMEM_DYN>>>(nullptr);  // S = QK^T
    softmax_k<<<BHH*TT, 256>>>();                             // P
    tc_gemm<4><<<dim3(1,16,BHH), 256, SMEM_DYN>>>(nullptr);   // y = PV
    tc_gemm<5><<<dim3(16,32), 256, SMEM_DYN>>>(out);          // out-proj
}